// round 8
// baseline (speedup 1.0000x reference)
#include <cuda_runtime.h>
#include <math.h>

#define NB 32
#define NS 1024
#define ND 256
#define NDS 64
#define NM 3
#define TS 128   // timesteps per out_kernel block

typedef unsigned long long ull;

// ---------------- scratch (device globals; no cudaMalloc allowed) ----------
__device__ float g_xp[(size_t)NB * NS * NM * NDS];   // [B][S][M*DS]  (XW@x + Xb + Hb)
__device__ float g_hn[(size_t)NB * NS * NM * NDS];   // [B][S][M*DS]  (h_new per step)

// ---------------- packed f32x2 helpers -------------------------------------
__device__ __forceinline__ void fma2(ull& acc, ull a, ull b) {
    asm("fma.rn.f32x2 %0, %1, %2, %0;" : "+l"(acc) : "l"(a), "l"(b));
}
__device__ __forceinline__ ull pack2(float x, float y) {
    ull r; asm("mov.b64 %0, {%1, %2};" : "=l"(r) : "f"(x), "f"(y)); return r;
}
__device__ __forceinline__ float2 unpack2(ull v) {
    float2 r; asm("mov.b64 {%0, %1}, %2;" : "=f"(r.x), "=f"(r.y) : "l"(v)); return r;
}
__device__ __forceinline__ float sum2(ull v) { float2 f = unpack2(v); return f.x + f.y; }

// ---------------- cp.async helpers ------------------------------------------
__device__ __forceinline__ void cp_async16(void* smem_dst, const void* gsrc) {
    unsigned s = (unsigned)__cvta_generic_to_shared(smem_dst);
    asm volatile("cp.async.ca.shared.global [%0], [%1], 16;" :: "r"(s), "l"(gsrc));
}
__device__ __forceinline__ void cp_commit() { asm volatile("cp.async.commit_group;"); }
__device__ __forceinline__ void cp_wait1()  { asm volatile("cp.async.wait_group 1;"); }

// ======================= Kernel 1: xp = XW@x + Xb + Hb =====================
// grid (S/64, B, M), block 256 (ty16 x tx16). Output tile: 64 t x 64 d, K=256.
__global__ void __launch_bounds__(256) xproj_kernel(
    const float* __restrict__ xa, const float* __restrict__ xv, const float* __restrict__ xl,
    const float* __restrict__ XW, const float* __restrict__ Xb, const float* __restrict__ Hb)
{
    __shared__ __align__(16) float Xs[64][64];   // [t][k]
    __shared__ __align__(16) float Wt[64][64];   // [k][d] (XW transposed)

    const int m  = blockIdx.z;
    const int bb = blockIdx.y;
    const int t0 = blockIdx.x * 64;
    const float* xm = (m == 0) ? xa : ((m == 1) ? xv : xl);

    const int tid = threadIdx.x;
    const int tx = tid & 15, ty = tid >> 4;

    ull acc[4][2] = {};

    const int ldx_row = tid >> 2, ldx_q = tid & 3;
    const int ldw_d = tid & 63, ldw_g = tid >> 6;

    for (int kc = 0; kc < 4; kc++) {
        __syncthreads();
        // load x tile [64 t][64 k]
        #pragma unroll
        for (int g = 0; g < 4; g++) {
            int col = ldx_q * 16 + g * 4;
            float4 v = *(const float4*)&xm[((size_t)(bb * NS) + t0 + ldx_row) * ND + kc * 64 + col];
            *(float4*)&Xs[ldx_row][col] = v;
        }
        // load XW[m] transposed into [k][d]
        #pragma unroll
        for (int g = 0; g < 4; g++) {
            int kk = ldw_g * 16 + g * 4;
            float4 w = *(const float4*)&XW[((size_t)(m * NDS + ldw_d)) * ND + kc * 64 + kk];
            Wt[kk + 0][ldw_d] = w.x; Wt[kk + 1][ldw_d] = w.y;
            Wt[kk + 2][ldw_d] = w.z; Wt[kk + 3][ldw_d] = w.w;
        }
        __syncthreads();
        #pragma unroll 16
        for (int kk = 0; kk < 64; kk++) {
            ull bv0 = *(const ull*)&Wt[kk][2 * tx];
            ull bv1 = *(const ull*)&Wt[kk][2 * tx + 32];
            #pragma unroll
            for (int i = 0; i < 4; i++) {
                float a = Xs[ty + 16 * i][kk];
                ull aa = pack2(a, a);
                fma2(acc[i][0], aa, bv0);
                fma2(acc[i][1], aa, bv1);
            }
        }
    }
    #pragma unroll
    for (int i = 0; i < 4; i++) {
        #pragma unroll
        for (int jp = 0; jp < 2; jp++) {
            int d0 = 2 * tx + 32 * jp;
            float2 v = unpack2(acc[i][jp]);
            float2 xb = *(const float2*)&Xb[m * NDS + d0];
            float2 hb = *(const float2*)&Hb[m * NDS + d0];
            v.x += xb.x + hb.x;
            v.y += xb.y + hb.y;
            *(float2*)&g_xp[((size_t)(bb * NS) + t0 + ty + 16 * i) * (NM * NDS) + m * NDS + d0] = v;
        }
    }
}

// ======================= Kernel 2: the sequential scan =====================
// grid = 32 (one block per batch element), 384 threads. All weights in regs.
__global__ void __launch_bounds__(384, 1) scan_kernel(
    const float* __restrict__ W1, const float* __restrict__ b1,
    const float* __restrict__ W2, const float* __restrict__ b2,
    const float* __restrict__ HW, const float* __restrict__ CW)
{
    __shared__ __align__(16) float sh_h[2][NM][NDS];  // double-buffered state
    __shared__ float sh_part[6][NDS];
    __shared__ float sh_z[NDS];
    __shared__ float sh_raw[16];
    __shared__ float sh_a[NM][NM];
    __shared__ float sh_b1[NDS];
    __shared__ float sh_W2[9 * NDS];
    __shared__ float sh_b2[12];

    const int u  = threadIdx.x;
    const int bb = blockIdx.x;

    // phase-1 mapping: output o1 (0..63), hc segment seg (0..5) of 32 elems
    const int o1  = u & 63;
    const int seg = u >> 6;
    // phase-4 mapping: output o2 = m*64+d (0..191), dot-half (0/1)
    const int half = u & 1;
    const int o2   = u >> 1;
    const int m4   = o2 >> 6;
    const int d4   = o2 & 63;
    const int s1 = (m4 == 0) ? 1 : 0;
    const int s2 = (m4 == 2) ? 1 : 2;
    const int src = half ? s2 : s1;

    // ---- weights into registers (packed f32 pairs) ----
    ull w1r[16];
    #pragma unroll
    for (int j = 0; j < 16; j++)
        w1r[j] = *(const ull*)(W1 + o1 * (NM * NDS) + seg * 32 + 2 * j);

    ull whw[16];   // HW[m4][d4][half*32 .. half*32+32)
    #pragma unroll
    for (int j = 0; j < 16; j++)
        whw[j] = *(const ull*)(HW + ((size_t)(m4 * NDS + d4)) * NDS + half * 32 + 2 * j);

    ull wcw[32];   // CW[m4][src][d4][0..64)
    #pragma unroll
    for (int j = 0; j < 32; j++)
        wcw[j] = *(const ull*)(CW + ((size_t)((m4 * NM + src) * NDS + d4)) * NDS + 2 * j);

    // ---- preload small constants into smem, zero h0 ----
    if (u < NDS) sh_b1[u] = b1[u];
    if (u < 9)   sh_b2[u] = b2[u];
    for (int i = u; i < 9 * NDS; i += 384) sh_W2[i] = W2[i];
    if (u < NM * NDS) (&sh_h[0][0][0])[u] = 0.0f;
    __syncthreads();

    const float* xp_base = g_xp + (size_t)bb * NS * (NM * NDS);
    float xp_c = __ldg(xp_base + o2);      // t = 0 (needed by half==0 only; both load)

    for (int t = 0; t < NS; t++) {
        const int cur = t & 1, nxt = cur ^ 1;
        const int tn = (t + 1 < NS) ? (t + 1) : t;
        float xp_n = __ldg(xp_base + (size_t)tn * (NM * NDS) + o2);  // prefetch

        // ---- phase 1: z-partials: W1 row o1, segment seg of hc ----
        const float* hseg = &sh_h[cur][0][0] + seg * 32;
        ull a1 = 0;
        #pragma unroll
        for (int j = 0; j < 16; j++)
            fma2(a1, *(const ull*)(hseg + 2 * j), w1r[j]);
        sh_part[seg][o1] = sum2(a1);
        __syncthreads();

        // ---- reduce to z = tanh(.) ----
        if (u < NDS) {
            float v = sh_b1[u];
            #pragma unroll
            for (int s = 0; s < 6; s++) v += sh_part[s][u];
            sh_z[u] = tanhf(v);
        }
        __syncthreads();

        // ---- raw[p] = z . W2[p] + b2[p], 9 warps ----
        if (u < 288) {
            int p = u >> 5, l = u & 31;
            float pr = sh_z[2 * l] * sh_W2[p * NDS + 2 * l]
                     + sh_z[2 * l + 1] * sh_W2[p * NDS + 2 * l + 1];
            #pragma unroll
            for (int off = 16; off; off >>= 1)
                pr += __shfl_down_sync(0xffffffffu, pr, off);
            if (l == 0) sh_raw[p] = pr + sh_b2[p];
        }
        __syncthreads();

        // ---- softmax rows (mask applied AFTER softmax, per reference) ----
        if (u < NM) {
            float r0 = sh_raw[u * 3 + 0], r1 = sh_raw[u * 3 + 1], r2 = sh_raw[u * 3 + 2];
            float mx = fmaxf(r0, fmaxf(r1, r2));
            float e0 = __expf(r0 - mx), e1 = __expf(r1 - mx), e2 = __expf(r2 - mx);
            float inv = 1.0f / (e0 + e1 + e2);
            sh_a[u][0] = (u == 0) ? 0.0f : e0 * inv;
            sh_a[u][1] = (u == 1) ? 0.0f : e1 * inv;
            sh_a[u][2] = (u == 2) ? 0.0f : e2 * inv;
        }
        __syncthreads();

        // ---- phase 4: su = HW.h + coupling + xp; h_new = silu(su) ----
        const float* hm = &sh_h[cur][m4][0] + half * 32;
        const float* hs = &sh_h[cur][src][0];
        ull ahw = 0, acw = 0;
        #pragma unroll
        for (int j = 0; j < 16; j++)
            fma2(ahw, *(const ull*)(hm + 2 * j), whw[j]);
        #pragma unroll
        for (int j = 0; j < 32; j++)
            fma2(acw, *(const ull*)(hs + 2 * j), wcw[j]);
        float val = sum2(ahw) + sh_a[m4][src] * sum2(acw);
        val += __shfl_xor_sync(0xffffffffu, val, 1);  // combine halves
        if (half == 0) {
            float su = val + xp_c;
            float hn = su / (1.0f + __expf(-su));     // silu
            sh_h[nxt][m4][d4] = hn;
            g_hn[((size_t)(bb * NS + t)) * (NM * NDS) + o2] = hn;
        }
        xp_c = xp_n;
        __syncthreads();
    }
}

// ======================= Kernel 3: y = OW@h_new + Ob; out = LN(y + x) ======
// grid (S/TS, B, M), block 256. Each thread owns output dim d = tid; OW row
// lives in registers. h_new streamed via double-buffered cp.async (8 t/group).
__global__ void __launch_bounds__(256) out_kernel(
    const float* __restrict__ xa, const float* __restrict__ xv, const float* __restrict__ xl,
    const float* __restrict__ OW, const float* __restrict__ Ob,
    const float* __restrict__ lng, const float* __restrict__ lnb,
    float* __restrict__ out)
{
    __shared__ __align__(16) float sh_ht[2][8][NDS];
    __shared__ float sh_red[2][8][2];

    const int tid = threadIdx.x;
    const int t0  = blockIdx.x * TS;
    const int bb  = blockIdx.y;
    const int m   = blockIdx.z;
    const float* xm = (m == 0) ? xa : ((m == 1) ? xv : xl);

    // OW[m][tid][0:64] in registers (32 packed pairs)
    ull ow[32];
    #pragma unroll
    for (int j = 0; j < 32; j++)
        ow[j] = *(const ull*)(OW + ((size_t)m * ND + tid) * NDS + 2 * j);
    const float ob = Ob[m * ND + tid];
    const float gg = lng[m * ND + tid];
    const float be = lnb[m * ND + tid];

    const float* hn_base = g_hn + ((size_t)(bb * NS + t0)) * (NM * NDS) + m * NDS;
    const float* x_base  = xm + ((size_t)bb * NS + t0) * ND;
    float* o_base = out + ((size_t)m * NB + bb) * (size_t)NS * ND + (size_t)t0 * ND;

    const int ptt = tid >> 4;   // 0..7 (t within group)
    const int pq  = tid & 15;   // float4 index within 64

    // prologue: prefetch group 0 into buf 0
    if (tid < 128) {
        int tc = min(0 * 8 + ptt, TS - 1);
        cp_async16(&sh_ht[0][ptt][pq * 4], hn_base + (size_t)tc * (NM * NDS) + pq * 4);
    }
    cp_commit();

    const int NG = TS / 8;
    for (int g = 0; g < NG; g++) {
        const int buf = g & 1;
        // prefetch next group into other buffer (clamped on the last group)
        if (tid < 128) {
            int tc = min((g + 1) * 8 + ptt, TS - 1);
            cp_async16(&sh_ht[buf ^ 1][ptt][pq * 4], hn_base + (size_t)tc * (NM * NDS) + pq * 4);
        }
        cp_commit();
        cp_wait1();            // group g complete (g+1 still in flight)
        __syncthreads();

        #pragma unroll
        for (int k = 0; k < 8; k++) {
            const int t = g * 8 + k;
            float xval = __ldg(x_base + (size_t)t * ND + tid);  // residual

            ull acc = 0;
            #pragma unroll
            for (int j = 0; j < 32; j++)
                fma2(acc, *(const ull*)&sh_ht[buf][k][2 * j], ow[j]);
            float v = sum2(acc) + ob + xval;

            // block LayerNorm over 256 dims
            float s = v, ss = v * v;
            #pragma unroll
            for (int off = 16; off; off >>= 1) {
                s  += __shfl_xor_sync(0xffffffffu, s, off);
                ss += __shfl_xor_sync(0xffffffffu, ss, off);
            }
            const int w = tid >> 5, l = tid & 31;
            const int rb = t & 1;
            if (l == 0) { sh_red[rb][w][0] = s; sh_red[rb][w][1] = ss; }
            __syncthreads();
            float S = 0.0f, SS = 0.0f;
            #pragma unroll
            for (int w2 = 0; w2 < 8; w2++) { S += sh_red[rb][w2][0]; SS += sh_red[rb][w2][1]; }
            float mu  = S * (1.0f / 256.0f);
            float var = SS * (1.0f / 256.0f) - mu * mu;
            float r   = rsqrtf(var + 1e-5f);
            o_base[(size_t)t * ND + tid] = (v - mu) * r * gg + be;
        }
    }
}

// =============================== launch ====================================
extern "C" void kernel_launch(void* const* d_in, const int* in_sizes, int n_in,
                              void* d_out, int out_size) {
    const float* xa  = (const float*)d_in[0];
    const float* xv  = (const float*)d_in[1];
    const float* xl  = (const float*)d_in[2];
    const float* XW  = (const float*)d_in[3];
    const float* Xb  = (const float*)d_in[4];
    const float* HW  = (const float*)d_in[5];
    const float* Hb  = (const float*)d_in[6];
    const float* OW  = (const float*)d_in[7];
    const float* Ob  = (const float*)d_in[8];
    const float* CW  = (const float*)d_in[9];
    const float* W1  = (const float*)d_in[10];
    const float* b1  = (const float*)d_in[11];
    const float* W2  = (const float*)d_in[12];
    const float* b2  = (const float*)d_in[13];
    const float* lng = (const float*)d_in[14];
    const float* lnb = (const float*)d_in[15];
    float* out = (float*)d_out;

    dim3 gA(NS / 64, NB, NM);
    xproj_kernel<<<gA, 256>>>(xa, xv, xl, XW, Xb, Hb);

    scan_kernel<<<NB, 384>>>(W1, b1, W2, b2, HW, CW);

    dim3 gC(NS / TS, NB, NM);
    out_kernel<<<gC, 256>>>(xa, xv, xl, OW, Ob, lng, lnb, out);
}